// round 14
// baseline (speedup 1.0000x reference)
#include <cuda_runtime.h>
#include <math.h>
#include <stdint.h>

// Problem constants (fixed by reference)
#define DIMN   2048
#define TSTEPS 256
#define KTOP   8
#define NPAIR  28
#define MSLOT  16
#define NDATA  512    // data threads
#define NTOT   544    // +1 serial warp
#define EPT    4      // 512*4 = 2048, contiguous per thread
#define NWD    16     // data warps
#define WCAP   32     // candidate slots per warp region
#define FULLM  0xffffffffu

#define SMEM_BYTES (80 * 1024)

// Upper-triangle pair tables, row-major (matches np.triu_indices(8, k=1))
__constant__ int c_iu[NPAIR] = {0,0,0,0,0,0,0,1,1,1,1,1,1,2,2,2,2,2,3,3,3,3,4,4,4,5,5,6};
__constant__ int c_ju[NPAIR] = {1,2,3,4,5,6,7,2,3,4,5,6,7,3,4,5,6,7,4,5,6,7,5,6,7,6,7,7};

__device__ __forceinline__ void warp_argmax(float& v, int& ix) {
#pragma unroll
    for (int off = 16; off; off >>= 1) {
        float ov = __shfl_xor_sync(FULLM, v, off);
        int   oi = __shfl_xor_sync(FULLM, ix, off);
        if (ov > v || (ov == v && oi < ix)) { v = ov; ix = oi; }
    }
}

__device__ __forceinline__ void upd_elem(float sr, float si, float dr, float di,
                                         float h, float tr, float tii, float eta,
                                         float& a, float& c) {
    float rc = h * (sr + dr), ic = h * (si + di);
    float aic = fabsf(ic);
    bool res = (rc >  1e-6f) && (aic <  rc);
    bool tor = (rc < -1e-6f) || (aic >= fabsf(rc));
    float kf = (res || tor) ? 1.f : 0.f;   // res & tor mutually exclusive
    float tf = tor ? 1.f : 0.f;
    a = sr + eta * (rc * kf + tf * tr);
    c = si + eta * (ic * kf + tf * tii);
}

__device__ __forceinline__ void cp_async16(void* dst_smem, const void* src) {
    unsigned u = (unsigned)__cvta_generic_to_shared(dst_smem);
    asm volatile("cp.async.cg.shared.global [%0], [%1], 16;" :: "r"(u), "l"(src));
}
#define CP_COMMIT()   asm volatile("cp.async.commit_group;")
#define CP_WAIT_ALL() asm volatile("cp.async.wait_group 0;")
#define CP_WAIT_1()   asm volatile("cp.async.wait_group 1;")

__device__ __forceinline__ void st_release_s32(int* p, int v) {
    unsigned u = (unsigned)__cvta_generic_to_shared(p);
    asm volatile("st.release.cta.shared.b32 [%0], %1;" :: "r"(u), "r"(v) : "memory");
}
__device__ __forceinline__ int ld_acquire_s32(int* p) {
    unsigned u = (unsigned)__cvta_generic_to_shared(p);
    int v;
    asm volatile("ld.acquire.cta.shared.b32 %0, [%1];" : "=r"(v) : "r"(u) : "memory");
    return v;
}
// data-warps-only barrier (serial warp does not participate)
#define BAR_DATA() asm volatile("bar.sync 1, %0;" :: "n"(NDATA) : "memory")

__global__ __launch_bounds__(NTOT, 1)
void me_bind_kernel(const float* __restrict__ x,
                    const float* __restrict__ tape_re,
                    const float* __restrict__ tape_im,
                    const float* __restrict__ eta_p,
                    const float* __restrict__ tb_re_g,
                    const float* __restrict__ tb_im_g,
                    float* __restrict__ out)
{
    extern __shared__ char smem_raw[];
    float* s_re   = (float*)smem_raw;            // [DIMN]
    float* s_im   = s_re + DIMN;                 // [DIMN]
    float* d_re   = s_im + DIMN;                 // [DIMN] corrected values (leader-written)
    float* d_im   = d_re + DIMN;                 // [DIMN]
    float* hbuf   = d_im + DIMN;                 // [3][DIMN] triple-buffered h
    float* tbres  = hbuf + 3 * DIMN;             // [DIMN]
    float* tbims  = tbres + DIMN;                // [DIMN]
    float* cand_val = tbims + DIMN;              // [NWD*WCAP]
    int*   cand_idx = (int*)(cand_val + NWD * WCAP);
    int*   wcnt   = cand_idx + NWD * WCAP;       // [NWD]
    int*   wflag  = wcnt + NWD;                  // [NWD] step-tagged publish flags
    float* wmax   = (float*)(wflag + NWD);       // [NWD]
    int*   top_idx = (int*)(wmax + NWD);         // [KTOP]
    float* top_sr = (float*)(top_idx + KTOP);    // [KTOP] staged s_re at top idx
    float* top_si = top_sr + KTOP;               // [KTOP]
    float* top_h  = top_si + KTOP;               // [KTOP]
    float* red    = top_h + KTOP;                // [NWD+2] partials + 2 dnorm parity slots
    float* rankv  = red + NWD + 2;               // [32] rank staging
    int*   ranki  = (int*)(rankv + 32);          // [32]
    unsigned* bmap = (unsigned*)(ranki + 32);    // [DIMN/32]

    const int tid  = threadIdx.x;
    const int lane = tid & 31;
    const int wid  = tid >> 5;
    const bool is_data = (wid < NWD);
    const int b    = blockIdx.x;
    const int eb   = tid * EPT;                  // contiguous element base
    const float eta = fabsf(eta_p[0]);

    // transient table: serial-warp lanes 0..15, one slot per lane, registers
    int   t_ti = 0, t_tj = 0, t_cnt = 0;
    float t_mre = 0.f, t_mim = 0.f;

    float sre[EPT], sim[EPT], tbr[EPT], tbi[EPT];

    const float* xb = x + (size_t)b * TSTEPS * DIMN;
    float*       ob = out + (size_t)b * TSTEPS * DIMN;

    // ---- init: s0 = renorm(tape) + SMEM mirrors + h(0),h(1) stream ----
    float psum = 0.f;
    if (is_data) {
        float4 tre = *(const float4*)(tape_re + eb);
        float4 tim = *(const float4*)(tape_im + eb);
        float4 br  = *(const float4*)(tb_re_g + eb);
        float4 bi  = *(const float4*)(tb_im_g + eb);
        sre[0]=tre.x; sre[1]=tre.y; sre[2]=tre.z; sre[3]=tre.w;
        sim[0]=tim.x; sim[1]=tim.y; sim[2]=tim.z; sim[3]=tim.w;
        tbr[0]=br.x;  tbr[1]=br.y;  tbr[2]=br.z;  tbr[3]=br.w;
        tbi[0]=bi.x;  tbi[1]=bi.y;  tbi[2]=bi.z;  tbi[3]=bi.w;
#pragma unroll
        for (int k = 0; k < EPT; k++) psum += sre[k]*sre[k] + sim[k]*sim[k];
        *(float4*)(tbres + eb) = br;
        *(float4*)(tbims + eb) = bi;
        cp_async16(hbuf + eb, xb + eb);                 // h(0) -> slot 0
        CP_COMMIT();
        cp_async16(hbuf + DIMN + eb, xb + DIMN + eb);   // h(1) -> slot 1
        CP_COMMIT();
    }
    if (tid < DIMN / 32) bmap[tid] = 0u;
    if (tid < NWD) wflag[tid] = 0;
    if (tid == 0) { red[NWD] = 0.f; red[NWD + 1] = 0.f; }
    {
#pragma unroll
        for (int off = 16; off; off >>= 1) psum += __shfl_xor_sync(FULLM, psum, off);
        if (is_data && lane == 0) red[wid] = psum;
        if (is_data) CP_WAIT_ALL();          // h(0), h(1) both landed
        __syncthreads();
        float tot = (lane < NWD) ? red[lane] : 0.f;
#pragma unroll
        for (int off = 16; off; off >>= 1) tot += __shfl_xor_sync(FULLM, tot, off);
        float inv = 1.f / fmaxf(sqrtf(tot), 1e-8f);
        if (is_data) {
#pragma unroll
            for (int k = 0; k < EPT; k++) { sre[k] *= inv; sim[k] *= inv; }
            *(float4*)(s_re + eb) = make_float4(sre[0],sre[1],sre[2],sre[3]);
            *(float4*)(s_im + eb) = make_float4(sim[0],sim[1],sim[2],sim[3]);
        }
    }
    __syncthreads();

    int hslot = 0;   // t % 3
    for (int t = 0; t < TSTEPS; t++) {
        float* hb = hbuf + hslot * DIMN;

        float cr[EPT], ci2[EPT], m2[EPT];
        if (is_data) {
            // ===== P1: read h(t) (landed), m2, warp max; issue h(t+2) ========
            float4 hq = *(float4*)(hb + eb);
            if (t + 2 < TSTEPS) {
                int ns = hslot + 2; if (ns >= 3) ns -= 3;   // (t+2)%3
                cp_async16(hbuf + ns * DIMN + eb,
                           xb + (size_t)(t + 2) * DIMN + eb);
                CP_COMMIT();
            }
            float hv[EPT] = {hq.x, hq.y, hq.z, hq.w};
#pragma unroll
            for (int k = 0; k < EPT; k++) {
                cr[k] = hv[k] * sre[k]; ci2[k] = hv[k] * sim[k];
                m2[k] = cr[k]*cr[k] + ci2[k]*ci2[k];
            }
            float lm = fmaxf(fmaxf(m2[0], m2[1]), fmaxf(m2[2], m2[3]));
            unsigned wm = __reduce_max_sync(FULLM, __float_as_uint(lm)); // m2>=0
            if (lane == 0) wmax[wid] = __uint_as_float(wm);

            BAR_DATA();   // (A) data-only: orders wmax + P4(t-1) among data

            // ===== P2: theta (multi-acc rank) + compaction + flag publish ====
            float v = (lane < NWD) ? wmax[lane] : -INFINITY;
            int r0 = 0, r1 = 0, r2 = 0, r3 = 0;
#pragma unroll
            for (int j = 0; j < NWD; j += 4) {
                float v0 = wmax[j],   v1 = wmax[j+1];
                float v2 = wmax[j+2], v3 = wmax[j+3];
                r0 += (v0 > v || (v0 == v && (j    ) < lane));
                r1 += (v1 > v || (v1 == v && (j + 1) < lane));
                r2 += (v2 > v || (v2 == v && (j + 2) < lane));
                r3 += (v3 > v || (v3 == v && (j + 3) < lane));
            }
            int rk = (r0 + r1) + (r2 + r3);
            unsigned b8 = __ballot_sync(FULLM, (lane < NWD) && (rk == KTOP - 1));
            float theta_sel = __shfl_sync(FULLM, v, __ffs(b8) - 1);

            int cnt = 0;
            const int base = wid * WCAP;
#pragma unroll
            for (int k = 0; k < EPT; k++) {
                bool c = m2[k] >= theta_sel;
                unsigned bal = __ballot_sync(FULLM, c);
                if (c) {
                    int pos = cnt + __popc(bal & ((1u << lane) - 1u));
                    if (pos < WCAP) {
                        cand_idx[base + pos] = eb + k;
                        cand_val[base + pos] = m2[k];
                    }
                }
                cnt += __popc(bal);
            }
            if (lane == 0) {
                wcnt[wid] = cnt;                 // plain STS, then release flag
                st_release_s32(&wflag[wid], t + 1);
            }

            // ===== elem math (overlaps serial warp) =========================
            float nre_[EPT], nim_[EPT];
            float ps = 0.f;
#pragma unroll
            for (int k = 0; k < EPT; k++) {
                float rc = cr[k], ic = ci2[k];
                float aic = fabsf(ic);
                bool res = (rc >  1e-6f) && (aic <  rc);
                bool tor = (rc < -1e-6f) || (aic >= fabsf(rc));
                float kf = (res || tor) ? 1.f : 0.f;
                float tf = tor ? 1.f : 0.f;
                float a  = sre[k] + eta * (rc * kf + tf * tbr[k]);
                float c2 = sim[k] + eta * (ic * kf + tf * tbi[k]);
                nre_[k] = a; nim_[k] = c2;
                ps += a * a + c2 * c2;
            }
#pragma unroll
            for (int off = 16; off; off >>= 1) ps += __shfl_xor_sync(FULLM, ps, off);
            if (lane == 0) red[wid] = ps;
            CP_WAIT_1();       // h(t+1) (issued a FULL step ago) landed;
                               // h(t+2) stays in flight
            __syncthreads();   // (C)

            // ===== P4: norm (LDS 4-acc sum + dnorm slot) + patch + write ====
            float t0 = 0.f, t1 = 0.f, t2 = 0.f, t3 = 0.f;
#pragma unroll
            for (int j = 0; j < NWD; j += 4) {
                t0 += red[j]; t1 += red[j+1]; t2 += red[j+2]; t3 += red[j+3];
            }
            float tot = ((t0 + t1) + (t2 + t3)) + red[NWD + (t & 1)];
            if (tid == 0) red[NWD + ((t + 1) & 1)] = 0.f;  // re-arm other slot
            float invn = 1.f / fmaxf(sqrtf(tot), 1e-8f);

            unsigned w = bmap[tid >> 3];
            unsigned nib = (w >> ((tid & 7) * 4)) & 0xFu;
            if (nib) {
#pragma unroll
                for (int k = 0; k < EPT; k++) {
                    if ((nib >> k) & 1u) {
                        int e = eb + k;
                        nre_[k] = d_re[e]; nim_[k] = d_im[e];   // no re-zeroing needed
                    }
                }
                atomicAnd(&bmap[tid >> 3], ~(nib << ((tid & 7) * 4)));
            }
            float4 fo, fr, fi;
#pragma unroll
            for (int k = 0; k < EPT; k++) {
                float a = nre_[k], c2 = nim_[k];
                float em = a * a + c2 * c2;
                float fa = a * invn, fc = c2 * invn;
                sre[k] = fa; sim[k] = fc;
                ((float*)&fr)[k] = fa;
                ((float*)&fi)[k] = fc;
                ((float*)&fo)[k] = sqrtf(em) * invn;
            }
            *(float4*)(s_re + eb) = fr;
            *(float4*)(s_im + eb) = fi;
            *(float4*)(ob + (size_t)t * DIMN + eb) = fo;
        } else {
            // =================== serial warp ================================
            // acquire-poll the 16 publish flags (proven; no nanosleep)
            {
                int tag = t + 1;
                int* fp = &wflag[lane & 15];
                while (ld_acquire_s32(fp) != tag) {}
            }
            // ---- gather: prefix walk over wcnt (LDS broadcast) ----
            int L = 0, srcw = -1, srcm = 0;
#pragma unroll
            for (int w2 = 0; w2 < NWD; w2++) {
                int cw = wcnt[w2];
                if (lane >= L && lane < L + cw) { srcw = w2; srcm = lane - L; }
                L += cw;
            }

            if (L <= 32) {
                float v = -INFINITY; int ix = 0x7fffffff;
                if (srcw >= 0) {
                    v  = cand_val[srcw * WCAP + srcm];
                    ix = cand_idx[srcw * WCAP + srcm];
                }
                rankv[lane] = v; ranki[lane] = ix;
                __syncwarp();
                int r0 = 0, r1 = 0, r2 = 0, r3 = 0;
#pragma unroll
                for (int j = 0; j < 32; j += 4) {
                    float v0 = rankv[j],   v1 = rankv[j+1];
                    float v2 = rankv[j+2], v3 = rankv[j+3];
                    int   x0 = ranki[j],   x1 = ranki[j+1];
                    int   x2 = ranki[j+2], x3 = ranki[j+3];
                    r0 += (v0 > v || (v0 == v && x0 < ix));
                    r1 += (v1 > v || (v1 == v && x1 < ix));
                    r2 += (v2 > v || (v2 == v && x2 < ix));
                    r3 += (v3 > v || (v3 == v && x3 < ix));
                }
                int rk = (r0 + r1) + (r2 + r3);
                if (srcw >= 0 && rk < KTOP) {
                    top_idx[rk] = ix;
                    top_sr[rk]  = s_re[ix];   // stage pair operands (parallel LDS)
                    top_si[rk]  = s_im[ix];
                    top_h[rk]   = hb[ix];
                }
            } else {
                // rare fallback: 8 knockout rounds over all 2048
                int sel[KTOP];
                for (int r = 0; r < KTOP; r++) {
                    float bv = -INFINITY; int bi = 0x7fffffff;
                    int e0 = lane * (DIMN / 32);
                    for (int q = 0; q < DIMN / 32; q++) {
                        int e = e0 + q;
                        bool skip = false;
                        for (int u = 0; u < r; u++) if (sel[u] == e) skip = true;
                        if (!skip) {
                            float h = hb[e];
                            float crr = h * s_re[e], cii = h * s_im[e];
                            float m = crr * crr + cii * cii;
                            if (m > bv) { bv = m; bi = e; }
                        }
                    }
                    float v = bv; int ix = bi;
                    warp_argmax(v, ix);
                    sel[r] = ix;
                    if (lane == 0) top_idx[r] = ix;
                }
                __syncwarp();
                if (lane < KTOP) {
                    int ix2 = top_idx[lane];
                    top_sr[lane] = s_re[ix2];
                    top_si[lane] = s_im[ix2];
                    top_h[lane]  = hb[ix2];
                }
            }
            __syncwarp();

            // ---- pair phase (operands from staging) ----
            int pci = 0, pcj = 0;
            float score = -INFINITY; bool pos = false;
            float sir = 0.f, sii = 0.f, sjr = 0.f, sji = 0.f;
            if (lane < NPAIR) {
                int iu = c_iu[lane], ju = c_ju[lane];
                pci = top_idx[iu];
                pcj = top_idx[ju];
                float hi_ = top_h[iu], hj_ = top_h[ju];
                sir = top_sr[iu]; sii = top_si[iu];
                sjr = top_sr[ju]; sji = top_si[ju];
                float cir = hi_ * sir, cii = hi_ * sii;
                float cjr = hj_ * sjr, cji = hj_ * sji;
                score = cir * cjr + cii * cji;
                pos = score > 0.f;
            }
            unsigned posb = __ballot_sync(FULLM, pos);
            int n_pos = __popc(posb);
            unsigned bound = 0u;
            float pmre = 0.f, pmim = 0.f;
            {
                float sv = pos ? score : -INFINITY;
                rankv[lane] = sv;
                __syncwarp();
                if (n_pos > 0) {
                    int n_bind = max(1, (int)((float)n_pos * 0.15f));   // f32 trunc
                    int th_idx = min(n_bind - 1, n_pos - 1);
                    int r0 = 0, r1 = 0, r2 = 0, r3 = 0;
#pragma unroll
                    for (int j = 0; j < NPAIR; j += 4) {
                        float v0 = rankv[j],   v1 = rankv[j+1];
                        float v2 = rankv[j+2], v3 = rankv[j+3];
                        r0 += (((posb >> (j  )) & 1u) && (v0 > sv || (v0 == sv && (j  ) < lane)));
                        r1 += (((posb >> (j+1)) & 1u) && (v1 > sv || (v1 == sv && (j+1) < lane)));
                        r2 += (((posb >> (j+2)) & 1u) && (v2 > sv || (v2 == sv && (j+2) < lane)));
                        r3 += (((posb >> (j+3)) & 1u) && (v3 > sv || (v3 == sv && (j+3) < lane)));
                    }
                    int rk2 = (r0 + r1) + (r2 + r3);
                    unsigned tb = __ballot_sync(FULLM, pos && (rk2 == th_idx));
                    float theta = __shfl_sync(FULLM, sv, __ffs(tb) - 1);
                    bound = __ballot_sync(FULLM, (lane < NPAIR) && (score >= theta));
                }
            }
            if (lane < NPAIR) {
                float pr = sir * sjr - sii * sji;
                float pi = sir * sji + sii * sjr;
                float mag = sqrtf(pr * pr + pi * pi);
                float sc = 0.05f / fmaxf(mag, 1e-8f);
                pmre = pr * sc; pmim = pi * sc;
            }

            // ---- PARALLEL transient update (== sequential 28-pair scan) ----
            {
                unsigned A0 = __ballot_sync(FULLM, (lane < MSLOT) && (t_cnt > 0)) & 0xffffu;
                bool isb = (lane < NPAIR) && ((bound >> lane) & 1u);
                unsigned mypack = (unsigned)pci | ((unsigned)pcj << 16);
                unsigned myrev  = (unsigned)pcj | ((unsigned)pci << 16);
                unsigned spack  = (unsigned)t_ti | ((unsigned)t_tj << 16);
                unsigned mm = 0u;
#pragma unroll
                for (int s2 = 0; s2 < MSLOT; s2++) {
                    unsigned sp = __shfl_sync(FULLM, spack, s2);
                    bool m = isb && ((A0 >> s2) & 1u) && (sp == mypack || sp == myrev);
                    mm |= m ? (1u << s2) : 0u;
                }
                unsigned refresh = __reduce_or_sync(FULLM, mm & (0u - mm));
                bool icand = isb && (mm == 0u);
                unsigned mykey = (unsigned)min(pci, pcj) | ((unsigned)max(pci, pcj) << 16);
                unsigned gkey = icand ? mykey : (0x80000000u | (unsigned)lane);
                unsigned grp = __match_any_sync(FULLM, gkey);
                bool leader = icand && ((int)(__ffs(grp) - 1) == lane);
                unsigned lmask = __ballot_sync(FULLM, leader);
                int nL = __popc(lmask);
                unsigned F = (~A0) & 0xffffu;
                if ((lane < MSLOT) && ((refresh >> lane) & 1u)) t_cnt = 5;
                bool doins = false; int srcl = 0;
                if ((lane < MSLOT) && ((F >> lane) & 1u)) {
                    int q = __popc(F & ((1u << lane) - 1u));
                    if (q < nL) { doins = true; srcl = (int)__fns(lmask, 0, q + 1); }
                }
                int   nti = __shfl_sync(FULLM, pci,  srcl);
                int   ntj = __shfl_sync(FULLM, pcj,  srcl);
                float nmr = __shfl_sync(FULLM, pmre, srcl);
                float nmi = __shfl_sync(FULLM, pmim, srcl);
                if (doins) { t_ti = nti; t_tj = ntj; t_mre = nmr; t_mim = nmi; t_cnt = 5; }
            }

            // ---- decay + liveness ----
            bool alive = false;
            if (lane < MSLOT) {
                t_mre *= 0.9f; t_mim *= 0.9f; t_cnt -= 1;
                alive = (t_cnt > 0) && (sqrtf(t_mre * t_mre + t_mim * t_mim) > 1e-6f);
                if (!alive) { t_cnt = 0; t_mre = 0.f; t_mim = 0.f; }
            }
            // endpoint mapping: lane l -> (slot l, ti), lane l+16 -> (slot l-16, tj)
            unsigned am = __ballot_sync(FULLM, alive);        // bits 0..15
            int slot = lane & 15;
            bool myact = ((am >> slot) & 1u) != 0u;
            int   tis = __shfl_sync(FULLM, t_ti,  slot);
            int   tjs = __shfl_sync(FULLM, t_tj,  slot);
            float mr  = __shfl_sync(FULLM, t_mre, slot);
            float mi  = __shfl_sync(FULLM, t_mim, slot);
            int   eidx = (lane < 16) ? tis : tjs;
            float ar = 0.1f * mr, ai = 0.1f * mi;             // my contribution

            // ---- corrections: shfl-collect per endpoint group (no atomics) --
            unsigned actm = am | (am << 16);
            if (myact) {
                unsigned peers = __match_any_sync(actm, eidx);
                bool leader = ((int)(__ffs(peers) - 1) == lane);
                // peers-group lanes share an identical mask -> convergent loop
                float dre = 0.f, dim = 0.f;
                unsigned pm = peers;
                while (pm) {
                    int p = __ffs(pm) - 1; pm &= pm - 1;
                    dre += __shfl_sync(peers, ar, p);
                    dim += __shfl_sync(peers, ai, p);
                }
                if (leader) {
                    float sr = s_re[eidx], si = s_im[eidx];
                    float h  = hb[eidx];
                    float tr = tbres[eidx], tii = tbims[eidx];
                    float a0, c0, a1, c1;
                    upd_elem(sr, si, 0.f, 0.f, h, tr, tii, eta, a0, c0);
                    upd_elem(sr, si, dre, dim, h, tr, tii, eta, a1, c1);
                    float dn = (a1 * a1 + c1 * c1) - (a0 * a0 + c0 * c0);
                    d_re[eidx] = a1; d_im[eidx] = c1;   // corrected, unnormalized
                    atomicOr(&bmap[eidx >> 5], 1u << (eidx & 31));
                    atomicAdd(&red[NWD + (t & 1)], dn); // <=4 leaders
                }
            }

            __syncthreads();   // (C) — serial warp's arrival
            // serial warp skips P4 and (A); next sync is C(t+1)
        }

        hslot++; if (hslot == 3) hslot = 0;
        // Ordering: P4(t) writes vs serial reads at t+1 — each data warp's
        // release-flag (P2, t+1) follows its P4(t) in program order; the
        // serial warp acquires all 16 flags before reading. Serial's
        // d_re/bmap/red-slot writes vs data P4 reads — ordered by barrier (C).
        // dnorm parity slots: slot (t&1) is read by data in P4(t) (after C),
        // and re-armed by tid0 in P4(t+1), which precedes (via warp0's flag)
        // any serial add at t+2. cand buffers of t+1 are rewritten only after
        // BAR_DATA(t+1); serial finished reading them before (C)(t).
    }
}

extern "C" void kernel_launch(void* const* d_in, const int* in_sizes, int n_in,
                              void* d_out, int out_size) {
    const float* x       = (const float*)d_in[0];
    const float* tape_re = (const float*)d_in[1];
    const float* tape_im = (const float*)d_in[2];
    const float* eta_p   = (const float*)d_in[3];
    const float* tb_re   = (const float*)d_in[4];
    const float* tb_im   = (const float*)d_in[5];
    float* out = (float*)d_out;

    static int attr_done = 0;
    if (!attr_done) {
        cudaFuncSetAttribute(me_bind_kernel,
                             cudaFuncAttributeMaxDynamicSharedMemorySize, SMEM_BYTES);
        attr_done = 1;
    }
    int B = in_sizes[0] / (TSTEPS * DIMN);   // 64
    me_bind_kernel<<<B, NTOT, SMEM_BYTES>>>(x, tape_re, tape_im, eta_p, tb_re, tb_im, out);
}

// round 16
// speedup vs baseline: 1.1457x; 1.1457x over previous
#include <cuda_runtime.h>
#include <math.h>
#include <stdint.h>

// Problem constants (fixed by reference)
#define DIMN   2048
#define TSTEPS 256
#define KTOP   8
#define NPAIR  28
#define MSLOT  16
#define NDATA  512    // data threads
#define NTOT   544    // +1 serial warp
#define EPT    4      // 512*4 = 2048, contiguous per thread
#define NWD    16     // data warps
#define WCAP   32     // candidate slots per warp region
#define FULLM  0xffffffffu

#define SMEM_BYTES (80 * 1024)

// Upper-triangle pair tables, row-major (matches np.triu_indices(8, k=1))
__constant__ int c_iu[NPAIR] = {0,0,0,0,0,0,0,1,1,1,1,1,1,2,2,2,2,2,3,3,3,3,4,4,4,5,5,6};
__constant__ int c_ju[NPAIR] = {1,2,3,4,5,6,7,2,3,4,5,6,7,3,4,5,6,7,4,5,6,7,5,6,7,6,7,7};

__device__ __forceinline__ void warp_argmax(float& v, int& ix) {
#pragma unroll
    for (int off = 16; off; off >>= 1) {
        float ov = __shfl_xor_sync(FULLM, v, off);
        int   oi = __shfl_xor_sync(FULLM, ix, off);
        if (ov > v || (ov == v && oi < ix)) { v = ov; ix = oi; }
    }
}

__device__ __forceinline__ void upd_elem(float sr, float si, float dr, float di,
                                         float h, float tr, float tii, float eta,
                                         float& a, float& c) {
    float rc = h * (sr + dr), ic = h * (si + di);
    float aic = fabsf(ic);
    bool res = (rc >  1e-6f) && (aic <  rc);
    bool tor = (rc < -1e-6f) || (aic >= fabsf(rc));
    float kf = (res || tor) ? 1.f : 0.f;   // res & tor mutually exclusive
    float tf = tor ? 1.f : 0.f;
    a = sr + eta * (rc * kf + tf * tr);
    c = si + eta * (ic * kf + tf * tii);
}

__device__ __forceinline__ void cp_async16(void* dst_smem, const void* src) {
    unsigned u = (unsigned)__cvta_generic_to_shared(dst_smem);
    asm volatile("cp.async.cg.shared.global [%0], [%1], 16;" :: "r"(u), "l"(src));
}
#define CP_COMMIT()   asm volatile("cp.async.commit_group;")
#define CP_WAIT_ALL() asm volatile("cp.async.wait_group 0;")
#define CP_WAIT_1()   asm volatile("cp.async.wait_group 1;")

// data-warps-only barrier (serial warp does not participate)
#define BAR_DATA() asm volatile("bar.sync 1, %0;" :: "n"(NDATA) : "memory")
// producer/consumer handoff barrier (id 2, all 544 threads counted):
// data warps ARRIVE (non-blocking, release), serial warp SYNCs (acquire).
#define BAR_HANDOFF_ARRIVE() asm volatile("bar.arrive 2, %0;" :: "n"(NTOT) : "memory")
#define BAR_HANDOFF_SYNC()   asm volatile("bar.sync 2, %0;"   :: "n"(NTOT) : "memory")

__global__ __launch_bounds__(NTOT, 1)
void me_bind_kernel(const float* __restrict__ x,
                    const float* __restrict__ tape_re,
                    const float* __restrict__ tape_im,
                    const float* __restrict__ eta_p,
                    const float* __restrict__ tb_re_g,
                    const float* __restrict__ tb_im_g,
                    float* __restrict__ out)
{
    extern __shared__ char smem_raw[];
    float* s_re   = (float*)smem_raw;            // [DIMN]
    float* s_im   = s_re + DIMN;                 // [DIMN]
    float* d_re   = s_im + DIMN;                 // [DIMN] sparse delta / corrected
    float* d_im   = d_re + DIMN;                 // [DIMN]
    float* hbuf   = d_im + DIMN;                 // [3][DIMN] triple-buffered h
    float* tbres  = hbuf + 3 * DIMN;             // [DIMN]
    float* tbims  = tbres + DIMN;                // [DIMN]
    float* cand_val = tbims + DIMN;              // [NWD*WCAP]
    int*   cand_idx = (int*)(cand_val + NWD * WCAP);
    int*   wcnt   = cand_idx + NWD * WCAP;       // [NWD]
    float* wmax   = (float*)(wcnt + NWD);        // [NWD]
    int*   top_idx = (int*)(wmax + NWD);         // [KTOP]
    float* red    = (float*)(top_idx + KTOP);    // [NWD+1] partials + serial dnorm
    float* rankv  = red + NWD + 1;               // [32] rank staging
    int*   ranki  = (int*)(rankv + 32);          // [32]
    unsigned* bmap = (unsigned*)(ranki + 32);    // [DIMN/32]

    const int tid  = threadIdx.x;
    const int lane = tid & 31;
    const int wid  = tid >> 5;
    const bool is_data = (wid < NWD);
    const int b    = blockIdx.x;
    const int eb   = tid * EPT;                  // contiguous element base
    const float eta = fabsf(eta_p[0]);

    // transient table: serial-warp lanes 0..15, one slot per lane, registers
    int   t_ti = 0, t_tj = 0, t_cnt = 0;
    float t_mre = 0.f, t_mim = 0.f;

    float sre[EPT], sim[EPT], tbr[EPT], tbi[EPT];

    const float* xb = x + (size_t)b * TSTEPS * DIMN;
    float*       ob = out + (size_t)b * TSTEPS * DIMN;

    // ---- init: s0 = renorm(tape) + SMEM mirrors + h(0),h(1) stream ----
    float psum = 0.f;
    if (is_data) {
        float4 tre = *(const float4*)(tape_re + eb);
        float4 tim = *(const float4*)(tape_im + eb);
        float4 br  = *(const float4*)(tb_re_g + eb);
        float4 bi  = *(const float4*)(tb_im_g + eb);
        sre[0]=tre.x; sre[1]=tre.y; sre[2]=tre.z; sre[3]=tre.w;
        sim[0]=tim.x; sim[1]=tim.y; sim[2]=tim.z; sim[3]=tim.w;
        tbr[0]=br.x;  tbr[1]=br.y;  tbr[2]=br.z;  tbr[3]=br.w;
        tbi[0]=bi.x;  tbi[1]=bi.y;  tbi[2]=bi.z;  tbi[3]=bi.w;
#pragma unroll
        for (int k = 0; k < EPT; k++) psum += sre[k]*sre[k] + sim[k]*sim[k];
        *(float4*)(tbres + eb) = br;
        *(float4*)(tbims + eb) = bi;
        *(float4*)(d_re + eb) = make_float4(0.f,0.f,0.f,0.f);
        *(float4*)(d_im + eb) = make_float4(0.f,0.f,0.f,0.f);
        cp_async16(hbuf + eb, xb + eb);                 // h(0) -> slot 0
        CP_COMMIT();
        cp_async16(hbuf + DIMN + eb, xb + DIMN + eb);   // h(1) -> slot 1
        CP_COMMIT();
    }
    if (tid < DIMN / 32) bmap[tid] = 0u;
    {
#pragma unroll
        for (int off = 16; off; off >>= 1) psum += __shfl_xor_sync(FULLM, psum, off);
        if (is_data && lane == 0) red[wid] = psum;
        if (is_data) CP_WAIT_ALL();          // h(0), h(1) both landed
        __syncthreads();
        float tot = (lane < NWD) ? red[lane] : 0.f;
#pragma unroll
        for (int off = 16; off; off >>= 1) tot += __shfl_xor_sync(FULLM, tot, off);
        float inv = 1.f / fmaxf(sqrtf(tot), 1e-8f);
        if (is_data) {
#pragma unroll
            for (int k = 0; k < EPT; k++) { sre[k] *= inv; sim[k] *= inv; }
            *(float4*)(s_re + eb) = make_float4(sre[0],sre[1],sre[2],sre[3]);
            *(float4*)(s_im + eb) = make_float4(sim[0],sim[1],sim[2],sim[3]);
        }
    }
    __syncthreads();

    int hslot = 0;   // t % 3
    for (int t = 0; t < TSTEPS; t++) {
        float* hb = hbuf + hslot * DIMN;

        float cr[EPT], ci2[EPT], m2[EPT];
        if (is_data) {
            // ===== P1: read h(t) (landed), m2, warp max; issue h(t+2) ========
            float4 hq = *(float4*)(hb + eb);
            if (t + 2 < TSTEPS) {
                int ns = hslot + 2; if (ns >= 3) ns -= 3;   // (t+2)%3
                cp_async16(hbuf + ns * DIMN + eb,
                           xb + (size_t)(t + 2) * DIMN + eb);
                CP_COMMIT();
            }
            float hv[EPT] = {hq.x, hq.y, hq.z, hq.w};
#pragma unroll
            for (int k = 0; k < EPT; k++) {
                cr[k] = hv[k] * sre[k]; ci2[k] = hv[k] * sim[k];
                m2[k] = cr[k]*cr[k] + ci2[k]*ci2[k];
            }
            float lm = fmaxf(fmaxf(m2[0], m2[1]), fmaxf(m2[2], m2[3]));
            unsigned wm = __reduce_max_sync(FULLM, __float_as_uint(lm)); // m2>=0
            if (lane == 0) wmax[wid] = __uint_as_float(wm);

            BAR_DATA();   // (A) data-only: orders wmax + P4(t-1) among data

            // ===== P2: theta (multi-acc rank) + compaction + handoff arrive ==
            float v = (lane < NWD) ? wmax[lane] : -INFINITY;
            int r0 = 0, r1 = 0, r2 = 0, r3 = 0;
#pragma unroll
            for (int j = 0; j < NWD; j += 4) {
                float v0 = wmax[j],   v1 = wmax[j+1];
                float v2 = wmax[j+2], v3 = wmax[j+3];
                r0 += (v0 > v || (v0 == v && (j    ) < lane));
                r1 += (v1 > v || (v1 == v && (j + 1) < lane));
                r2 += (v2 > v || (v2 == v && (j + 2) < lane));
                r3 += (v3 > v || (v3 == v && (j + 3) < lane));
            }
            int rk = (r0 + r1) + (r2 + r3);
            unsigned b8 = __ballot_sync(FULLM, (lane < NWD) && (rk == KTOP - 1));
            float theta_sel = __shfl_sync(FULLM, v, __ffs(b8) - 1);

            int cnt = 0;
            const int base = wid * WCAP;
#pragma unroll
            for (int k = 0; k < EPT; k++) {
                bool c = m2[k] >= theta_sel;
                unsigned bal = __ballot_sync(FULLM, c);
                if (c) {
                    int pos = cnt + __popc(bal & ((1u << lane) - 1u));
                    if (pos < WCAP) {
                        cand_idx[base + pos] = eb + k;
                        cand_val[base + pos] = m2[k];
                    }
                }
                cnt += __popc(bal);
            }
            if (lane == 0) wcnt[wid] = cnt;
            // release: candidates + wcnt + P4(t-1) state published to serial
            BAR_HANDOFF_ARRIVE();   // non-blocking; proceed to elem math

            // ===== elem math (overlaps serial warp) =========================
            float nre_[EPT], nim_[EPT];
            float ps = 0.f;
#pragma unroll
            for (int k = 0; k < EPT; k++) {
                float rc = cr[k], ic = ci2[k];
                float aic = fabsf(ic);
                bool res = (rc >  1e-6f) && (aic <  rc);
                bool tor = (rc < -1e-6f) || (aic >= fabsf(rc));
                float kf = (res || tor) ? 1.f : 0.f;
                float tf = tor ? 1.f : 0.f;
                float a  = sre[k] + eta * (rc * kf + tf * tbr[k]);
                float c2 = sim[k] + eta * (ic * kf + tf * tbi[k]);
                nre_[k] = a; nim_[k] = c2;
                ps += a * a + c2 * c2;
            }
#pragma unroll
            for (int off = 16; off; off >>= 1) ps += __shfl_xor_sync(FULLM, ps, off);
            if (lane == 0) red[wid] = ps;
            CP_WAIT_1();       // h(t+1) (issued a FULL step ago) landed;
                               // h(t+2) stays in flight
            __syncthreads();   // (C)

            // ===== P4: norm (LDS 4-acc sum) + patch + vector write ==========
            float t0 = 0.f, t1 = 0.f, t2 = 0.f, t3 = 0.f;
#pragma unroll
            for (int j = 0; j < NWD; j += 4) {
                t0 += red[j]; t1 += red[j+1]; t2 += red[j+2]; t3 += red[j+3];
            }
            float tot = ((t0 + t1) + (t2 + t3)) + red[NWD];
            float invn = 1.f / fmaxf(sqrtf(tot), 1e-8f);

            unsigned w = bmap[tid >> 3];
            unsigned nib = (w >> ((tid & 7) * 4)) & 0xFu;
            if (nib) {
#pragma unroll
                for (int k = 0; k < EPT; k++) {
                    if ((nib >> k) & 1u) {
                        int e = eb + k;
                        nre_[k] = d_re[e]; nim_[k] = d_im[e];
                        d_re[e] = 0.f; d_im[e] = 0.f;
                    }
                }
                atomicAnd(&bmap[tid >> 3], ~(nib << ((tid & 7) * 4)));
            }
            float4 fo, fr, fi;
#pragma unroll
            for (int k = 0; k < EPT; k++) {
                float a = nre_[k], c2 = nim_[k];
                float em = a * a + c2 * c2;
                float fa = a * invn, fc = c2 * invn;
                sre[k] = fa; sim[k] = fc;
                ((float*)&fr)[k] = fa;
                ((float*)&fi)[k] = fc;
                ((float*)&fo)[k] = sqrtf(em) * invn;
            }
            *(float4*)(s_re + eb) = fr;
            *(float4*)(s_im + eb) = fi;
            *(float4*)(ob + (size_t)t * DIMN + eb) = fo;
        } else {
            // =================== serial warp ================================
            // HW-sleep until all 512 data threads arrived (post-compaction).
            // bar.sync acquires their released STS (cand, wcnt, P4(t-1)).
            BAR_HANDOFF_SYNC();

            // ---- gather: prefix walk over wcnt (LDS broadcast) ----
            int L = 0, srcw = -1, srcm = 0;
#pragma unroll
            for (int w2 = 0; w2 < NWD; w2++) {
                int cw = wcnt[w2];
                if (lane >= L && lane < L + cw) { srcw = w2; srcm = lane - L; }
                L += cw;
            }

            if (L <= 32) {
                float v = -INFINITY; int ix = 0x7fffffff;
                if (srcw >= 0) {
                    v  = cand_val[srcw * WCAP + srcm];
                    ix = cand_idx[srcw * WCAP + srcm];
                }
                rankv[lane] = v; ranki[lane] = ix;
                __syncwarp();
                int r0 = 0, r1 = 0, r2 = 0, r3 = 0;
#pragma unroll
                for (int j = 0; j < 32; j += 4) {
                    float v0 = rankv[j],   v1 = rankv[j+1];
                    float v2 = rankv[j+2], v3 = rankv[j+3];
                    int   x0 = ranki[j],   x1 = ranki[j+1];
                    int   x2 = ranki[j+2], x3 = ranki[j+3];
                    r0 += (v0 > v || (v0 == v && x0 < ix));
                    r1 += (v1 > v || (v1 == v && x1 < ix));
                    r2 += (v2 > v || (v2 == v && x2 < ix));
                    r3 += (v3 > v || (v3 == v && x3 < ix));
                }
                int rk = (r0 + r1) + (r2 + r3);
                if (srcw >= 0 && rk < KTOP) top_idx[rk] = ix;
            } else {
                // rare fallback: 8 knockout rounds over all 2048
                int sel[KTOP];
                for (int r = 0; r < KTOP; r++) {
                    float bv = -INFINITY; int bi = 0x7fffffff;
                    int e0 = lane * (DIMN / 32);
                    for (int q = 0; q < DIMN / 32; q++) {
                        int e = e0 + q;
                        bool skip = false;
                        for (int u = 0; u < r; u++) if (sel[u] == e) skip = true;
                        if (!skip) {
                            float h = hb[e];
                            float crr = h * s_re[e], cii = h * s_im[e];
                            float m = crr * crr + cii * cii;
                            if (m > bv) { bv = m; bi = e; }
                        }
                    }
                    float v = bv; int ix = bi;
                    warp_argmax(v, ix);
                    sel[r] = ix;
                    if (lane == 0) top_idx[r] = ix;
                }
            }
            __syncwarp();

            // ---- pair phase ----
            int pci = 0, pcj = 0;
            float score = -INFINITY; bool pos = false;
            float sir = 0.f, sii = 0.f, sjr = 0.f, sji = 0.f;
            if (lane < NPAIR) {
                pci = top_idx[c_iu[lane]];
                pcj = top_idx[c_ju[lane]];
                float hi_ = hb[pci], hj_ = hb[pcj];
                sir = s_re[pci]; sii = s_im[pci];
                sjr = s_re[pcj]; sji = s_im[pcj];
                float cir = hi_ * sir, cii = hi_ * sii;
                float cjr = hj_ * sjr, cji = hj_ * sji;
                score = cir * cjr + cii * cji;
                pos = score > 0.f;
            }
            unsigned posb = __ballot_sync(FULLM, pos);
            int n_pos = __popc(posb);
            unsigned bound = 0u;
            float pmre = 0.f, pmim = 0.f;
            {
                float sv = pos ? score : -INFINITY;
                rankv[lane] = sv;
                __syncwarp();
                if (n_pos > 0) {
                    int n_bind = max(1, (int)((float)n_pos * 0.15f));   // f32 trunc
                    int th_idx = min(n_bind - 1, n_pos - 1);
                    int r0 = 0, r1 = 0, r2 = 0, r3 = 0;
#pragma unroll
                    for (int j = 0; j < NPAIR; j += 4) {
                        float v0 = rankv[j],   v1 = rankv[j+1];
                        float v2 = rankv[j+2], v3 = rankv[j+3];
                        r0 += (((posb >> (j  )) & 1u) && (v0 > sv || (v0 == sv && (j  ) < lane)));
                        r1 += (((posb >> (j+1)) & 1u) && (v1 > sv || (v1 == sv && (j+1) < lane)));
                        r2 += (((posb >> (j+2)) & 1u) && (v2 > sv || (v2 == sv && (j+2) < lane)));
                        r3 += (((posb >> (j+3)) & 1u) && (v3 > sv || (v3 == sv && (j+3) < lane)));
                    }
                    int rk2 = (r0 + r1) + (r2 + r3);
                    unsigned tb = __ballot_sync(FULLM, pos && (rk2 == th_idx));
                    float theta = __shfl_sync(FULLM, sv, __ffs(tb) - 1);
                    bound = __ballot_sync(FULLM, (lane < NPAIR) && (score >= theta));
                }
            }
            if (lane < NPAIR) {
                float pr = sir * sjr - sii * sji;
                float pi = sir * sji + sii * sjr;
                float mag = sqrtf(pr * pr + pi * pi);
                float sc = 0.05f / fmaxf(mag, 1e-8f);
                pmre = pr * sc; pmim = pi * sc;
            }

            // ---- PARALLEL transient update (== sequential 28-pair scan) ----
            {
                unsigned A0 = __ballot_sync(FULLM, (lane < MSLOT) && (t_cnt > 0)) & 0xffffu;
                bool isb = (lane < NPAIR) && ((bound >> lane) & 1u);
                unsigned mypack = (unsigned)pci | ((unsigned)pcj << 16);
                unsigned myrev  = (unsigned)pcj | ((unsigned)pci << 16);
                unsigned spack  = (unsigned)t_ti | ((unsigned)t_tj << 16);
                unsigned mm = 0u;
#pragma unroll
                for (int s2 = 0; s2 < MSLOT; s2++) {
                    unsigned sp = __shfl_sync(FULLM, spack, s2);
                    bool m = isb && ((A0 >> s2) & 1u) && (sp == mypack || sp == myrev);
                    mm |= m ? (1u << s2) : 0u;
                }
                unsigned refresh = __reduce_or_sync(FULLM, mm & (0u - mm));
                bool icand = isb && (mm == 0u);
                unsigned mykey = (unsigned)min(pci, pcj) | ((unsigned)max(pci, pcj) << 16);
                unsigned gkey = icand ? mykey : (0x80000000u | (unsigned)lane);
                unsigned grp = __match_any_sync(FULLM, gkey);
                bool leader = icand && ((int)(__ffs(grp) - 1) == lane);
                unsigned lmask = __ballot_sync(FULLM, leader);
                int nL = __popc(lmask);
                unsigned F = (~A0) & 0xffffu;
                if ((lane < MSLOT) && ((refresh >> lane) & 1u)) t_cnt = 5;
                bool doins = false; int srcl = 0;
                if ((lane < MSLOT) && ((F >> lane) & 1u)) {
                    int q = __popc(F & ((1u << lane) - 1u));
                    if (q < nL) { doins = true; srcl = (int)__fns(lmask, 0, q + 1); }
                }
                int   nti = __shfl_sync(FULLM, pci,  srcl);
                int   ntj = __shfl_sync(FULLM, pcj,  srcl);
                float nmr = __shfl_sync(FULLM, pmre, srcl);
                float nmi = __shfl_sync(FULLM, pmim, srcl);
                if (doins) { t_ti = nti; t_tj = ntj; t_mre = nmr; t_mim = nmi; t_cnt = 5; }
            }

            // ---- decay + liveness ----
            bool alive = false;
            if (lane < MSLOT) {
                t_mre *= 0.9f; t_mim *= 0.9f; t_cnt -= 1;
                alive = (t_cnt > 0) && (sqrtf(t_mre * t_mre + t_mim * t_mim) > 1e-6f);
                if (!alive) { t_cnt = 0; t_mre = 0.f; t_mim = 0.f; }
            }
            unsigned am = __ballot_sync(FULLM, alive);        // bits 0..15
            int slot = lane & 15;
            bool myact = ((am >> slot) & 1u) != 0u;
            int   tis = __shfl_sync(FULLM, t_ti,  slot);
            int   tjs = __shfl_sync(FULLM, t_tj,  slot);
            float mr  = __shfl_sync(FULLM, t_mre, slot);
            float mi  = __shfl_sync(FULLM, t_mim, slot);
            int eidx = (lane < 16) ? tis : tjs;
            if (myact) {
                atomicAdd(&d_re[eidx], 0.1f * mr);
                atomicAdd(&d_im[eidx], 0.1f * mi);
            }
            __syncwarp();
            // ---- sparse corrections: one leader per unique affected index ----
            float dnorm = 0.f;
            unsigned actm = am | (am << 16);
            if (myact) {
                unsigned peers = __match_any_sync(actm, eidx);
                if ((int)(__ffs(peers) - 1) == lane) {
                    float dre = d_re[eidx], dim = d_im[eidx];
                    float sr = s_re[eidx], si = s_im[eidx];
                    float h  = hb[eidx];
                    float tr = tbres[eidx], tii = tbims[eidx];
                    float a0, c0, a1, c1;
                    upd_elem(sr, si, 0.f, 0.f, h, tr, tii, eta, a0, c0);
                    upd_elem(sr, si, dre, dim, h, tr, tii, eta, a1, c1);
                    dnorm = (a1 * a1 + c1 * c1) - (a0 * a0 + c0 * c0);
                    d_re[eidx] = a1; d_im[eidx] = c1;   // corrected, unnormalized
                    atomicOr(&bmap[eidx >> 5], 1u << (eidx & 31));
                }
            }
#pragma unroll
            for (int off = 16; off; off >>= 1)
                dnorm += __shfl_xor_sync(FULLM, dnorm, off);
            if (lane == 0) red[NWD] = dnorm;

            __syncthreads();   // (C) — serial warp's arrival
            // serial warp skips P4 and (A); next sync is handoff(t+1)
        }

        hslot++; if (hslot == 3) hslot = 0;
        // Ordering: P4(t) writes vs serial reads at t+1 — each data warp's
        // handoff ARRIVE (t+1) follows its P4(t) in program order, and the
        // serial warp's handoff SYNC acquires them. Serial's d_re/bmap/red
        // writes vs data P4 reads — ordered by barrier (C). cand buffers of
        // t+1 are rewritten only after BAR_DATA(t+1); the serial warp
        // finished reading them before (C)(t).
    }
}

extern "C" void kernel_launch(void* const* d_in, const int* in_sizes, int n_in,
                              void* d_out, int out_size) {
    const float* x       = (const float*)d_in[0];
    const float* tape_re = (const float*)d_in[1];
    const float* tape_im = (const float*)d_in[2];
    const float* eta_p   = (const float*)d_in[3];
    const float* tb_re   = (const float*)d_in[4];
    const float* tb_im   = (const float*)d_in[5];
    float* out = (float*)d_out;

    static int attr_done = 0;
    if (!attr_done) {
        cudaFuncSetAttribute(me_bind_kernel,
                             cudaFuncAttributeMaxDynamicSharedMemorySize, SMEM_BYTES);
        attr_done = 1;
    }
    int B = in_sizes[0] / (TSTEPS * DIMN);   // 64
    me_bind_kernel<<<B, NTOT, SMEM_BYTES>>>(x, tape_re, tape_im, eta_p, tb_re, tb_im, out);
}